// round 12
// baseline (speedup 1.0000x reference)
#include <cuda_runtime.h>

#define EPSV   1e-7f
#define BB     64
#define DD     256
#define NSPLIT 64

// Scratch (zero-initialized device globals; no allocations allowed).
__device__ float        g_part[BB * NSPLIT * DD];   // 4 MB
__device__ float        g_zpart[BB * NSPLIT];
__device__ unsigned int g_cnt[BB];                  // self-resetting ticket

__device__ __forceinline__ float tanh_approx(float v) {
    float r;
    asm("tanh.approx.f32 %0, %1;" : "=f"(r) : "f"(v));
    return r;
}

#define DOT8(d, p0, p1)                \
    do {                               \
        d = (p0).x * w0.x;             \
        d = fmaf((p0).y, w0.y, d);     \
        d = fmaf((p0).z, w0.z, d);     \
        d = fmaf((p0).w, w0.w, d);     \
        d = fmaf((p1).x, w1.x, d);     \
        d = fmaf((p1).y, w1.y, d);     \
        d = fmaf((p1).z, w1.z, d);     \
        d = fmaf((p1).w, w1.w, d);     \
    } while (0)

#define ACC8(e, p0, p1)                \
    do {                               \
        acc0 = fmaf((p0).x, e, acc0);  \
        acc1 = fmaf((p0).y, e, acc1);  \
        acc2 = fmaf((p0).z, e, acc2);  \
        acc3 = fmaf((p0).w, e, acc3);  \
        acc4 = fmaf((p1).x, e, acc4);  \
        acc5 = fmaf((p1).y, e, acc5);  \
        acc6 = fmaf((p1).z, e, acc6);  \
        acc7 = fmaf((p1).w, e, acc7);  \
    } while (0)

#define COMPUTE2(A0, A1, B0, B1, trow)                                   \
    do {                                                                 \
        float s0, s1;                                                    \
        DOT8(s0, A0, A1);                                                \
        DOT8(s1, B0, B1);                                                \
        _Pragma("unroll")                                                \
        for (int sh = 16; sh > 0; sh >>= 1) {                            \
            s0 += __shfl_xor_sync(0xffffffffu, s0, sh);                  \
            s1 += __shfl_xor_sync(0xffffffffu, s1, sh);                  \
        }                                                                \
        const float e0 = __expf(tanh_approx(s0 + __ldg(bv + (trow))));   \
        const float e1 = __expf(tanh_approx(s1 + __ldg(bv + (trow)+1))); \
        zloc += e0 + e1;                                                 \
        ACC8(e0, A0, A1);                                                \
        ACC8(e1, B0, B1);                                                \
    } while (0)

#define LOAD2(A0, A1, B0, B1, tr)                                        \
    do {                                                                 \
        const float4* _r = xb + (size_t)(tr) * (DD/4);                   \
        A0 = __ldcs(_r +       lane);                                    \
        A1 = __ldcs(_r +  32 + lane);                                    \
        B0 = __ldcs(_r +  64 + lane);                                    \
        B1 = __ldcs(_r +  96 + lane);                                    \
    } while (0)

// grid (B, NSPLIT=64), block 128 = 4 warps, 16 rows per warp.
// Register double-buffered 2-row steps (next step's 4 LDG.128 in flight
// during this step's shuffle/tanh tail).
__global__ void __launch_bounds__(128, 8) attn_k(
    const float* __restrict__ x, const float* __restrict__ W,
    const float* __restrict__ bv, int T, float* __restrict__ out)
{
    const int b    = blockIdx.x;
    const int sp   = blockIdx.y;
    const int tid  = threadIdx.x;
    const int lane = tid & 31;
    const int warp = tid >> 5;
    const int tileRows = T / NSPLIT;                 // 64
    const int rowsPerWarp = tileRows >> 2;           // 16
    const int t0   = sp * tileRows + warp * rowsPerWarp;

    const float4 w0 = __ldg((const float4*)W + lane);
    const float4 w1 = __ldg((const float4*)W + 32 + lane);

    float acc0=0.f, acc1=0.f, acc2=0.f, acc3=0.f;
    float acc4=0.f, acc5=0.f, acc6=0.f, acc7=0.f;
    float zloc = 0.f;

    const float4* xb = (const float4*)(x) + (size_t)b * T * (DD/4);

    float4 pA0, pA1, pB0, pB1;   // buffer P
    float4 qA0, qA1, qB0, qB1;   // buffer Q

    LOAD2(pA0, pA1, pB0, pB1, t0);

    #pragma unroll 2
    for (int i = 0; i < rowsPerWarp; i += 4) {
        const int t = t0 + i;
        LOAD2(qA0, qA1, qB0, qB1, t + 2);
        COMPUTE2(pA0, pA1, pB0, pB1, t);
        int tn = t + 4;
        if (tn >= t0 + rowsPerWarp) tn = t0;          // harmless redundant load
        LOAD2(pA0, pA1, pB0, pB1, tn);
        COMPUTE2(qA0, qA1, qB0, qB1, t + 2);
    }

    // ---- block reduction across 4 warps (block = 128 threads, DD = 256) ----
    __shared__ float sacc[4][DD];
    __shared__ float sz[4];
    __shared__ int   s_last;
    const int j0 = lane * 4;
    sacc[warp][j0 + 0]       = acc0;
    sacc[warp][j0 + 1]       = acc1;
    sacc[warp][j0 + 2]       = acc2;
    sacc[warp][j0 + 3]       = acc3;
    sacc[warp][128 + j0 + 0] = acc4;
    sacc[warp][128 + j0 + 1] = acc5;
    sacc[warp][128 + j0 + 2] = acc6;
    sacc[warp][128 + j0 + 3] = acc7;
    if (lane == 0) sz[warp] = zloc;
    __syncthreads();

    // each thread owns columns tid and tid+128
    float r0 = 0.f, r1 = 0.f;
    #pragma unroll
    for (int w = 0; w < 4; w++) {
        r0 += sacc[w][tid];
        r1 += sacc[w][tid + 128];
    }
    float* gp = &g_part[(b * NSPLIT + sp) * DD];
    gp[tid]       = r0;
    gp[tid + 128] = r1;
    if (tid == 0) {
        float z = (sz[0] + sz[1]) + (sz[2] + sz[3]);
        g_zpart[b * NSPLIT + sp] = z;
    }

    __threadfence();
    __syncthreads();
    if (tid == 0) {
        unsigned int old = atomicAdd(&g_cnt[b], 1u);
        s_last = (old == NSPLIT - 1);
    }
    __syncthreads();

    if (s_last) {
        __threadfence();
        float tot0 = 0.f, tot1 = 0.f, z = 0.f;
        #pragma unroll 8
        for (int s2 = 0; s2 < NSPLIT; s2++) {
            const float* p = &g_part[(b * NSPLIT + s2) * DD];
            tot0 += p[tid];
            tot1 += p[tid + 128];
        }
        #pragma unroll 8
        for (int s2 = 0; s2 < NSPLIT; s2++)
            z += g_zpart[b * NSPLIT + s2];
        const float inv = 1.0f / (z + EPSV);
        out[b * DD + tid]       = tot0 * inv;
        out[b * DD + tid + 128] = tot1 * inv;
        if (tid == 0) g_cnt[b] = 0;   // self-reset for graph replay
    }
}

extern "C" void kernel_launch(void* const* d_in, const int* in_sizes, int n_in,
                              void* d_out, int out_size) {
    const float* x  = (const float*)d_in[0];
    const float* W  = (const float*)d_in[1];
    const float* bv = (const float*)d_in[2];
    float* out = (float*)d_out;

    const int D = in_sizes[1];            // 256
    const int T = in_sizes[2];            // 4096
    const int B = in_sizes[0] / (T * D);  // 64

    dim3 grid(B, NSPLIT);
    attn_k<<<grid, 128>>>(x, W, bv, T, out);
}

// round 14
// speedup vs baseline: 1.0880x; 1.0880x over previous
#include <cuda_runtime.h>

#define EPSV   1e-7f
#define BB     64
#define DD     256
#define NSPLIT 8

// Scratch (zero-initialized device globals; no allocations allowed).
__device__ float        g_part[BB * NSPLIT * DD];
__device__ float        g_zpart[BB * NSPLIT];
__device__ unsigned int g_cnt[BB];      // self-resetting ticket

__device__ __forceinline__ float tanh_approx(float v) {
    float r;
    asm("tanh.approx.f32 %0, %1;" : "=f"(r) : "f"(v));
    return r;
}

#define DOT8(d, p0, p1)                \
    do {                               \
        d = (p0).x * w0.x;             \
        d = fmaf((p0).y, w0.y, d);     \
        d = fmaf((p0).z, w0.z, d);     \
        d = fmaf((p0).w, w0.w, d);     \
        d = fmaf((p1).x, w1.x, d);     \
        d = fmaf((p1).y, w1.y, d);     \
        d = fmaf((p1).z, w1.z, d);     \
        d = fmaf((p1).w, w1.w, d);     \
    } while (0)

#define ACC8(e, p0, p1)                \
    do {                               \
        acc0 = fmaf((p0).x, e, acc0);  \
        acc1 = fmaf((p0).y, e, acc1);  \
        acc2 = fmaf((p0).z, e, acc2);  \
        acc3 = fmaf((p0).w, e, acc3);  \
        acc4 = fmaf((p1).x, e, acc4);  \
        acc5 = fmaf((p1).y, e, acc5);  \
        acc6 = fmaf((p1).z, e, acc6);  \
        acc7 = fmaf((p1).w, e, acc7);  \
    } while (0)

#define COMPUTE2(A0, A1, B0, B1, trow)                                   \
    do {                                                                 \
        float s0, s1;                                                    \
        DOT8(s0, A0, A1);                                                \
        DOT8(s1, B0, B1);                                                \
        _Pragma("unroll")                                                \
        for (int sh = 16; sh > 0; sh >>= 1) {                            \
            s0 += __shfl_xor_sync(0xffffffffu, s0, sh);                  \
            s1 += __shfl_xor_sync(0xffffffffu, s1, sh);                  \
        }                                                                \
        const float e0 = __expf(tanh_approx(s0 + __ldg(bv + (trow))));   \
        const float e1 = __expf(tanh_approx(s1 + __ldg(bv + (trow)+1))); \
        zloc += e0 + e1;                                                 \
        ACC8(e0, A0, A1);                                                \
        ACC8(e1, B0, B1);                                                \
    } while (0)

#define LOAD2(A0, A1, B0, B1, tr)                                        \
    do {                                                                 \
        const float4* _r = xb + (size_t)(tr) * (DD/4);                   \
        A0 = _r[       lane];                                            \
        A1 = _r[ 32 +  lane];                                            \
        B0 = _r[ 64 +  lane];                                            \
        B1 = _r[ 96 +  lane];                                            \
    } while (0)

// grid (B=64, NSPLIT=8) = 512 CTAs -> fully resident single wave (4 CTA/SM cap).
// block 256 = 8 warps, 64 rows per warp, register double-buffered 2-row steps.
__global__ void __launch_bounds__(256, 4) attn_k(
    const float* __restrict__ x, const float* __restrict__ W,
    const float* __restrict__ bv, int T, float* __restrict__ out)
{
    const int b    = blockIdx.x;
    const int sp   = blockIdx.y;
    const int tid  = threadIdx.x;
    const int lane = tid & 31;
    const int warp = tid >> 5;
    const int tileRows = T / NSPLIT;                 // 512
    const int rowsPerWarp = tileRows >> 3;           // 64
    const int t0   = sp * tileRows + warp * rowsPerWarp;

    const float4 w0 = __ldg((const float4*)W + lane);
    const float4 w1 = __ldg((const float4*)W + 32 + lane);

    float acc0=0.f, acc1=0.f, acc2=0.f, acc3=0.f;
    float acc4=0.f, acc5=0.f, acc6=0.f, acc7=0.f;
    float zloc = 0.f;

    const float4* xb = (const float4*)(x) + (size_t)b * T * (DD/4);

    float4 pA0, pA1, pB0, pB1;   // buffer P
    float4 qA0, qA1, qB0, qB1;   // buffer Q

    LOAD2(pA0, pA1, pB0, pB1, t0);

    #pragma unroll 2
    for (int i = 0; i < rowsPerWarp; i += 4) {
        const int t = t0 + i;
        LOAD2(qA0, qA1, qB0, qB1, t + 2);
        COMPUTE2(pA0, pA1, pB0, pB1, t);
        int tn = t + 4;
        if (tn >= t0 + rowsPerWarp) tn = t0;          // harmless redundant load
        LOAD2(pA0, pA1, pB0, pB1, tn);
        COMPUTE2(qA0, qA1, qB0, qB1, t + 2);
    }

    // ---- block reduction across 8 warps ----
    __shared__ float sacc[8][DD];
    __shared__ float sz[8];
    __shared__ int   s_last;
    const int j0 = lane * 4;
    sacc[warp][j0 + 0]       = acc0;
    sacc[warp][j0 + 1]       = acc1;
    sacc[warp][j0 + 2]       = acc2;
    sacc[warp][j0 + 3]       = acc3;
    sacc[warp][128 + j0 + 0] = acc4;
    sacc[warp][128 + j0 + 1] = acc5;
    sacc[warp][128 + j0 + 2] = acc6;
    sacc[warp][128 + j0 + 3] = acc7;
    if (lane == 0) sz[warp] = zloc;
    __syncthreads();

    float s = 0.f;
    #pragma unroll
    for (int w = 0; w < 8; w++) s += sacc[w][tid];
    g_part[(b * NSPLIT + sp) * DD + tid] = s;
    if (tid == 0) {
        float z = 0.f;
        #pragma unroll
        for (int w = 0; w < 8; w++) z += sz[w];
        g_zpart[b * NSPLIT + sp] = z;
    }

    __threadfence();
    __syncthreads();
    if (tid == 0) {
        unsigned int old = atomicAdd(&g_cnt[b], 1u);
        s_last = (old == NSPLIT - 1);
    }
    __syncthreads();

    if (s_last) {
        __threadfence();
        float tot = 0.f, z = 0.f;
        #pragma unroll
        for (int s2 = 0; s2 < NSPLIT; s2++)
            tot += g_part[(b * NSPLIT + s2) * DD + tid];
        #pragma unroll
        for (int s2 = 0; s2 < NSPLIT; s2++)
            z += g_zpart[b * NSPLIT + s2];
        out[b * DD + tid] = tot / (z + EPSV);
        if (tid == 0) g_cnt[b] = 0;   // self-reset for graph replay
    }
}

extern "C" void kernel_launch(void* const* d_in, const int* in_sizes, int n_in,
                              void* d_out, int out_size) {
    const float* x  = (const float*)d_in[0];
    const float* W  = (const float*)d_in[1];
    const float* bv = (const float*)d_in[2];
    float* out = (float*)d_out;

    const int D = in_sizes[1];            // 256
    const int T = in_sizes[2];            // 4096
    const int B = in_sizes[0] / (T * D);  // 64

    dim3 grid(B, NSPLIT);
    attn_k<<<grid, 256>>>(x, W, bv, T, out);
}